// round 14
// baseline (speedup 1.0000x reference)
#include <cuda_runtime.h>
#include <cstdint>

#define NB 16384      // B
#define NK 50         // K
#define NH 64         // H
#define REG 0.01
#define DEPTH 3       // cp.async ring depth (stages)
#define NSTAGE 13     // 12 full stages of 4 items + 1 tail stage of 2
#define WPB 8         // warps per block
#define UPW 2         // users per warp (sequential) -> grid = 1024 = single wave
#define TPB (WPB * 32)

typedef unsigned long long u64;

static __device__ __forceinline__ u64 pack2(float lo, float hi) {
    u64 r; asm("mov.b64 %0, {%1,%2};" : "=l"(r) : "f"(lo), "f"(hi)); return r;
}
static __device__ __forceinline__ void unpack2(u64 v, float& lo, float& hi) {
    asm("mov.b64 {%0,%1}, %2;" : "=f"(lo), "=f"(hi) : "l"(v));
}
static __device__ __forceinline__ u64 add2(u64 a, u64 b) {
    u64 r; asm("add.rn.f32x2 %0, %1, %2;" : "=l"(r) : "l"(a), "l"(b)); return r;
}
static __device__ __forceinline__ u64 mul2(u64 a, u64 b) {
    u64 r; asm("mul.rn.f32x2 %0, %1, %2;" : "=l"(r) : "l"(a), "l"(b)); return r;
}
static __device__ __forceinline__ u64 fma2(u64 a, u64 b, u64 c) {
    u64 r; asm("fma.rn.f32x2 %0, %1, %2, %3;" : "=l"(r) : "l"(a), "l"(b), "l"(c)); return r;
}
static __device__ __forceinline__ void cpa16(uint32_t dst, const void* src) {
    asm volatile("cp.async.cg.shared.global [%0], [%1], 16;\n" :: "r"(dst), "l"(src));
}

__device__ double g_mse, g_ue, g_ie;        // zero-init; self-reset each run
__device__ unsigned int g_count;

__global__ __launch_bounds__(TPB, 8) void mf_main(
    const float* __restrict__ user_weight,   // [100000, 64]
    const float* __restrict__ item_weight,   // [1000000, 64]
    const float* __restrict__ user_bias,     // [100000, 1]
    const float* __restrict__ item_bias,     // [1000000, 1]
    const float* __restrict__ bias,          // [1]
    const float* __restrict__ target,        // [B, K]
    const int*   __restrict__ user,          // [B]
    const int*   __restrict__ item,          // [B, K]
    float* __restrict__ out)                 // [B*K + 1]
{
    const int tid  = threadIdx.x;
    const int warp = tid >> 5;
    const int lane = tid & 31;
    const int g    = lane >> 3;              // group 0..3 within warp
    const int s    = lane & 7;               // H-slice owner (32B each)

    __shared__ int   s_items[WPB * UPW * NK];
    __shared__ float s_pred[WPB * UPW * NK];
    __shared__ __align__(16) char s_ring[WPB * DEPTH * 4 * 256];  // 24 KB

    const int base = blockIdx.x * WPB * UPW * NK;
    for (int i = tid; i < WPB * UPW * NK; i += TPB) s_items[i] = item[base + i];

    const float bias0 = __ldg(bias);
    const uint32_t my_ring =
        (uint32_t)__cvta_generic_to_shared(s_ring) + warp * (DEPTH * 1024)
        + g * 256 + s * 32;

    __syncthreads();

    float mse_ie_ue[3] = {0.f, 0.f, 0.f};    // [0]=unused here; see below
    float ie_acc = 0.0f;                      // valid on s==0 lanes (both users)
    float ue_sum = 0.0f;                      // valid on all lanes after reduce

    #pragma unroll
    for (int uu = 0; uu < UPW; uu++) {
        const int b = blockIdx.x * (WPB * UPW) + warp * UPW + uu;
        const int* myitems = s_items + (warp * UPW + uu) * NK;
        float* mypred = s_pred + (warp * UPW + uu) * NK;

        // --- user embedding slice: contiguous floats [8s .. 8s+7] ---
        const int u = user[b];
        const float ubv = __ldg(user_bias + u);
        const u64 ubp = pack2(ubv, ubv);
        const float* uwr = user_weight + (size_t)u * NH + s * 8;
        ulonglong2 ur0 = __ldg((const ulonglong2*)uwr);
        ulonglong2 ur1 = __ldg((const ulonglong2*)(uwr + 4));
        const u64 u0 = add2(ur0.x, ubp);
        const u64 u1 = add2(ur0.y, ubp);
        const u64 u2 = add2(ur1.x, ubp);
        const u64 u3 = add2(ur1.y, ubp);

        // stage t item index for this group (tail stage: groups >=2 fetch a
        // dummy valid row, never consumed)
        #define STAGE_K(t) (((t) < 12) ? (4 * (t) + g) : ((g < 2) ? (48 + g) : g))
        #define SLOT(t) (((t) % DEPTH) * 1024)

        // --- prologue: fill stages 0..DEPTH-2 ---
        #pragma unroll
        for (int t = 0; t < DEPTH - 1; t++) {
            const int idx = myitems[STAGE_K(t)];
            const float* row = item_weight + (size_t)idx * NH + s * 8;
            const uint32_t dst = my_ring + SLOT(t);
            cpa16(dst, row);
            cpa16(dst + 16, row + 4);
            asm volatile("cp.async.commit_group;\n");
        }
        float fb[2];
        fb[0] = __ldg(item_bias + myitems[STAGE_K(0)]);
        fb[1] = __ldg(item_bias + myitems[STAGE_K(1)]);

        #pragma unroll
        for (int t = 0; t < NSTAGE; t++) {
            if (t + DEPTH - 1 < NSTAGE) {
                const int tt = t + DEPTH - 1;
                const int idx = myitems[STAGE_K(tt)];
                const float* row = item_weight + (size_t)idx * NH + s * 8;
                const uint32_t dst = my_ring + SLOT(tt);
                cpa16(dst, row);
                cpa16(dst + 16, row + 4);
            }
            asm volatile("cp.async.commit_group;\n");

            const float ib = fb[t & 1];
            if (t + 2 < NSTAGE)
                fb[t & 1] = __ldg(item_bias + myitems[STAGE_K(t + 2)]);

            asm volatile("cp.async.wait_group %0;\n" :: "n"(DEPTH - 1));

            const uint32_t srcp = my_ring + SLOT(t);
            u64 x0, x1, x2, x3;
            asm volatile("ld.shared.v2.u64 {%0,%1}, [%2];"
                         : "=l"(x0), "=l"(x1) : "r"(srcp));
            asm volatile("ld.shared.v2.u64 {%0,%1}, [%2];"
                         : "=l"(x2), "=l"(x3) : "r"(srcp + 16));

            const u64 ibp = pack2(ib, ib);
            x0 = add2(x0, ibp); x1 = add2(x1, ibp);
            x2 = add2(x2, ibp); x3 = add2(x3, ibp);
            u64 d2 = mul2(u0, x0); d2 = fma2(u1, x1, d2);
            d2 = fma2(u2, x2, d2); d2 = fma2(u3, x3, d2);
            u64 q2 = mul2(x0, x0); q2 = fma2(x1, x1, q2);
            q2 = fma2(x2, x2, q2); q2 = fma2(x3, x3, q2);
            float dl, dh, ql, qh;
            unpack2(d2, dl, dh); unpack2(q2, ql, qh);
            float d = dl + dh, q = ql + qh;
            #pragma unroll
            for (int o = 1; o < 8; o <<= 1) {
                d += __shfl_xor_sync(0xffffffffu, d, o);
                q += __shfl_xor_sync(0xffffffffu, q, o);
            }
            const bool active = (t < 12) || (g < 2);
            if (s == 0 && active) {
                mypred[STAGE_K(t)] = d + bias0;
                ie_acc += sqrtf(q);
            }
        }
        #undef STAGE_K
        #undef SLOT

        // --- ||ue|| for this user ---
        u64 uq2 = mul2(u0, u0); uq2 = fma2(u1, u1, uq2);
        uq2 = fma2(u2, u2, uq2); uq2 = fma2(u3, u3, uq2);
        float ul, uh; unpack2(uq2, ul, uh);
        float uq = ul + uh;
        #pragma unroll
        for (int o = 1; o < 8; o <<= 1)
            uq += __shfl_xor_sync(0xffffffffu, uq, o);
        ue_sum += sqrtf(uq);                  // valid on every s==0 lane
    }

    __syncwarp();

    // --- coalesced epilogue: 100 contiguous preds per warp ---
    float mse_acc = 0.0f;
    const int wbase = blockIdx.x * (WPB * UPW) * NK + warp * UPW * NK;
    #pragma unroll
    for (int i = lane; i < UPW * NK; i += 32) {
        const float pred = s_pred[warp * UPW * NK + i];
        const float diff = pred - __ldcs(target + wbase + i);
        mse_acc = fmaf(diff, diff, mse_acc);
        __stcs(out + wbase + i, pred);
    }
    #pragma unroll
    for (int o = 1; o < 32; o <<= 1)
        mse_acc += __shfl_xor_sync(0xffffffffu, mse_acc, o);

    // reduce ie / ue across the four s==0 lanes (0,8,16,24)
    float e  = (s == 0) ? ie_acc : 0.0f;
    float un = (s == 0) ? ue_sum : 0.0f;
    e  += __shfl_xor_sync(0xffffffffu, e, 8);
    e  += __shfl_xor_sync(0xffffffffu, e, 16);
    un += __shfl_xor_sync(0xffffffffu, un, 8);
    un += __shfl_xor_sync(0xffffffffu, un, 16);
    un *= 0.25f;   // the four s==0 lanes each hold the full per-user sum

    __shared__ float sm[WPB], se[WPB], su[WPB];
    if (lane == 0) { sm[warp] = mse_acc; se[warp] = e; su[warp] = un; }
    __syncthreads();

    if (tid == 0) {
        float tm = 0.f, te = 0.f, tu = 0.f;
        #pragma unroll
        for (int i = 0; i < WPB; i++) { tm += sm[i]; te += se[i]; tu += su[i]; }
        atomicAdd(&g_mse, (double)tm);
        atomicAdd(&g_ie,  (double)te);
        atomicAdd(&g_ue,  (double)tu);
        __threadfence();
        const unsigned old = atomicAdd(&g_count, 1u);
        if (old == gridDim.x - 1) {
            u64 mb  = atomicExch((u64*)&g_mse, 0ull);
            u64 eb  = atomicExch((u64*)&g_ie,  0ull);
            u64 ub2 = atomicExch((u64*)&g_ue,  0ull);
            const double mse = __longlong_as_double((long long)mb);
            const double ie  = __longlong_as_double((long long)eb);
            const double ue  = __longlong_as_double((long long)ub2);
            const double n_bk = (double)NB * (double)NK;
            out[NB * NK] = (float)(mse / n_bk + REG * (ue / (double)NB)
                                              + REG * (ie / n_bk));
            atomicExch(&g_count, 0u);
        }
    }
}

extern "C" void kernel_launch(void* const* d_in, const int* in_sizes, int n_in,
                              void* d_out, int out_size) {
    const float* user_weight = (const float*)d_in[0];
    const float* item_weight = (const float*)d_in[1];
    const float* user_bias   = (const float*)d_in[2];
    const float* item_bias   = (const float*)d_in[3];
    const float* bias        = (const float*)d_in[4];
    const float* target      = (const float*)d_in[5];
    const int*   user        = (const int*)d_in[6];
    const int*   item        = (const int*)d_in[7];

    mf_main<<<NB / (WPB * UPW), TPB>>>(user_weight, item_weight, user_bias,
                                       item_bias, bias, target, user, item,
                                       (float*)d_out);
}

// round 15
// speedup vs baseline: 1.0502x; 1.0502x over previous
#include <cuda_runtime.h>
#include <cstdint>

#define NB 16384      // B
#define NK 50         // K
#define NH 64         // H
#define REG 0.01
#define DEPTH 3       // cp.async ring depth (stages)
#define NSTAGE 13     // 12 full stages of 4 items + 1 tail stage of 2
#define WPB 8         // warps per block (one user each)
#define TPB (WPB * 32)

typedef unsigned long long u64;

static __device__ __forceinline__ u64 pack2(float lo, float hi) {
    u64 r; asm("mov.b64 %0, {%1,%2};" : "=l"(r) : "f"(lo), "f"(hi)); return r;
}
static __device__ __forceinline__ void unpack2(u64 v, float& lo, float& hi) {
    asm("mov.b64 {%0,%1}, %2;" : "=f"(lo), "=f"(hi) : "l"(v));
}
static __device__ __forceinline__ u64 add2(u64 a, u64 b) {
    u64 r; asm("add.rn.f32x2 %0, %1, %2;" : "=l"(r) : "l"(a), "l"(b)); return r;
}
static __device__ __forceinline__ u64 mul2(u64 a, u64 b) {
    u64 r; asm("mul.rn.f32x2 %0, %1, %2;" : "=l"(r) : "l"(a), "l"(b)); return r;
}
static __device__ __forceinline__ u64 fma2(u64 a, u64 b, u64 c) {
    u64 r; asm("fma.rn.f32x2 %0, %1, %2, %3;" : "=l"(r) : "l"(a), "l"(b), "l"(c)); return r;
}
static __device__ __forceinline__ void cpa16(uint32_t dst, const void* src) {
    asm volatile("cp.async.cg.shared.global [%0], [%1], 16;\n" :: "r"(dst), "l"(src));
}

__device__ double g_mse, g_ue, g_ie;        // zero-init; self-reset each run
__device__ unsigned int g_count;

__global__ __launch_bounds__(TPB, 8) void mf_main(
    const float* __restrict__ user_weight,   // [100000, 64]
    const float* __restrict__ item_weight,   // [1000000, 64]
    const float* __restrict__ user_bias,     // [100000, 1]
    const float* __restrict__ item_bias,     // [1000000, 1]
    const float* __restrict__ bias,          // [1]
    const float* __restrict__ target,        // [B, K]
    const int*   __restrict__ user,          // [B]
    const int*   __restrict__ item,          // [B, K]
    float* __restrict__ out)                 // [B*K + 1]
{
    const int tid  = threadIdx.x;
    const int warp = tid >> 5;               // WPB warps, one user each
    const int lane = tid & 31;
    const int g    = lane >> 3;              // group 0..3 within warp
    const int s    = lane & 7;               // H-slice owner (32B each)
    const int b    = blockIdx.x * WPB + warp;

    __shared__ int   s_items[WPB * NK];
    __shared__ float s_pred[WPB * NK];
    __shared__ __align__(16) char s_ring[WPB * DEPTH * 4 * 256];  // 24 KB

    const int base = blockIdx.x * WPB * NK;
    for (int i = tid; i < WPB * NK; i += TPB) s_items[i] = item[base + i];

    // --- user embedding slice: contiguous floats [8s .. 8s+7] ---
    const int u = user[b];
    const float ubv = __ldg(user_bias + u);
    const u64 ubp = pack2(ubv, ubv);
    const float* uwr = user_weight + (size_t)u * NH + s * 8;
    ulonglong2 ur0 = __ldg((const ulonglong2*)uwr);
    ulonglong2 ur1 = __ldg((const ulonglong2*)(uwr + 4));
    const u64 u0 = add2(ur0.x, ubp);
    const u64 u1 = add2(ur0.y, ubp);
    const u64 u2 = add2(ur1.x, ubp);
    const u64 u3 = add2(ur1.y, ubp);
    const float bias0 = __ldg(bias);

    __syncthreads();
    const int* myitems = s_items + warp * NK;
    const uint32_t my_ring =
        (uint32_t)__cvta_generic_to_shared(s_ring) + warp * (DEPTH * 1024)
        + g * 256 + s * 32;

    // stage t item index for this group (tail stage covers only k=48,49 on
    // groups 0,1; groups 2,3 issue NO fetch for the tail — see ISSUE below)
    #define STAGE_K(t) (((t) < 12) ? (4 * (t) + g) : ((g < 2) ? (48 + g) : g))
    #define SLOT(t) (((t) % DEPTH) * 1024)

    // --- prologue: fill stages 0..DEPTH-2 (always full stages) ---
    #pragma unroll
    for (int t = 0; t < DEPTH - 1; t++) {
        const int idx = myitems[STAGE_K(t)];
        const float* row = item_weight + (size_t)idx * NH + s * 8;
        const uint32_t dst = my_ring + SLOT(t);
        cpa16(dst, row);
        cpa16(dst + 16, row + 4);
        asm volatile("cp.async.commit_group;\n");
    }
    // bias register pipeline (depth 2)
    float fb[2];
    fb[0] = __ldg(item_bias + myitems[STAGE_K(0)]);
    fb[1] = __ldg(item_bias + myitems[STAGE_K(1)]);

    float ie_acc = 0.0f;                     // valid on s==0 lanes

    #pragma unroll
    for (int t = 0; t < NSTAGE; t++) {
        // issue stage t+DEPTH-1 (tail stage: only groups 0,1 fetch — saves
        // 2 dummy 256B rows per warp, ~4.5% of DRAM traffic). commit_group
        // stays uniform; empty groups complete immediately.
        if (t + DEPTH - 1 < NSTAGE) {
            const int tt = t + DEPTH - 1;
            if (tt < 12 || g < 2) {
                const int idx = myitems[STAGE_K(tt)];
                const float* row = item_weight + (size_t)idx * NH + s * 8;
                const uint32_t dst = my_ring + SLOT(tt);
                cpa16(dst, row);
                cpa16(dst + 16, row + 4);
            }
        }
        asm volatile("cp.async.commit_group;\n");

        const float ib = fb[t & 1];
        if (t + 2 < NSTAGE)
            fb[t & 1] = __ldg(item_bias + myitems[STAGE_K(t + 2)]);

        // stage t guaranteed complete when <= DEPTH-1 newer groups pending
        asm volatile("cp.async.wait_group %0;\n" :: "n"(DEPTH - 1));

        // consume own 32B slice (tail stage, groups 2,3: stale-but-finite
        // data; result discarded by `active` below)
        const uint32_t srcp = my_ring + SLOT(t);
        u64 x0, x1, x2, x3;
        asm volatile("ld.shared.v2.u64 {%0,%1}, [%2];"
                     : "=l"(x0), "=l"(x1) : "r"(srcp));
        asm volatile("ld.shared.v2.u64 {%0,%1}, [%2];"
                     : "=l"(x2), "=l"(x3) : "r"(srcp + 16));

        const u64 ibp = pack2(ib, ib);
        x0 = add2(x0, ibp); x1 = add2(x1, ibp);
        x2 = add2(x2, ibp); x3 = add2(x3, ibp);
        u64 d2 = mul2(u0, x0); d2 = fma2(u1, x1, d2);
        d2 = fma2(u2, x2, d2); d2 = fma2(u3, x3, d2);
        u64 q2 = mul2(x0, x0); q2 = fma2(x1, x1, q2);
        q2 = fma2(x2, x2, q2); q2 = fma2(x3, x3, q2);
        float dl, dh, ql, qh;
        unpack2(d2, dl, dh); unpack2(q2, ql, qh);
        float d = dl + dh, q = ql + qh;
        #pragma unroll
        for (int o = 1; o < 8; o <<= 1) {
            d += __shfl_xor_sync(0xffffffffu, d, o);
            q += __shfl_xor_sync(0xffffffffu, q, o);
        }
        const bool active = (t < 12) || (g < 2);
        if (s == 0 && active) {
            s_pred[warp * NK + STAGE_K(t)] = d + bias0;
            ie_acc += sqrtf(q);
        }
    }
    #undef STAGE_K
    #undef SLOT

    __syncwarp();

    // --- coalesced epilogue: preds out, targets in, mse per lane ---
    float mse_acc = 0.0f;
    #pragma unroll
    for (int i = lane; i < NK; i += 32) {
        const float pred = s_pred[warp * NK + i];
        const float diff = pred - __ldcs(target + b * NK + i);
        mse_acc = fmaf(diff, diff, mse_acc);
        __stcs(out + b * NK + i, pred);
    }
    #pragma unroll
    for (int o = 1; o < 32; o <<= 1)
        mse_acc += __shfl_xor_sync(0xffffffffu, mse_acc, o);

    // --- ||ue|| ---
    u64 uq2 = mul2(u0, u0); uq2 = fma2(u1, u1, uq2);
    uq2 = fma2(u2, u2, uq2); uq2 = fma2(u3, u3, uq2);
    float ul, uh; unpack2(uq2, ul, uh);
    float uq = ul + uh;
    #pragma unroll
    for (int o = 1; o < 8; o <<= 1)
        uq += __shfl_xor_sync(0xffffffffu, uq, o);
    const float ue_n = sqrtf(uq);             // valid on every s==0 lane

    // reduce ie across the four s==0 lanes (0,8,16,24)
    float e = (s == 0) ? ie_acc : 0.0f;
    e += __shfl_xor_sync(0xffffffffu, e, 8);
    e += __shfl_xor_sync(0xffffffffu, e, 16);

    __shared__ float sm[WPB], se[WPB], su[WPB];
    if (lane == 0) { sm[warp] = mse_acc; se[warp] = e; su[warp] = ue_n; }
    __syncthreads();

    if (tid == 0) {
        float tm = 0.f, te = 0.f, tu = 0.f;
        #pragma unroll
        for (int i = 0; i < WPB; i++) { tm += sm[i]; te += se[i]; tu += su[i]; }
        atomicAdd(&g_mse, (double)tm);
        atomicAdd(&g_ie,  (double)te);
        atomicAdd(&g_ue,  (double)tu);
        __threadfence();
        const unsigned old = atomicAdd(&g_count, 1u);
        if (old == gridDim.x - 1) {
            u64 mb  = atomicExch((u64*)&g_mse, 0ull);
            u64 eb  = atomicExch((u64*)&g_ie,  0ull);
            u64 ub2 = atomicExch((u64*)&g_ue,  0ull);
            const double mse = __longlong_as_double((long long)mb);
            const double ie  = __longlong_as_double((long long)eb);
            const double ue  = __longlong_as_double((long long)ub2);
            const double n_bk = (double)NB * (double)NK;
            out[NB * NK] = (float)(mse / n_bk + REG * (ue / (double)NB)
                                              + REG * (ie / n_bk));
            atomicExch(&g_count, 0u);
        }
    }
}

extern "C" void kernel_launch(void* const* d_in, const int* in_sizes, int n_in,
                              void* d_out, int out_size) {
    const float* user_weight = (const float*)d_in[0];
    const float* item_weight = (const float*)d_in[1];
    const float* user_bias   = (const float*)d_in[2];
    const float* item_bias   = (const float*)d_in[3];
    const float* bias        = (const float*)d_in[4];
    const float* target      = (const float*)d_in[5];
    const int*   user        = (const int*)d_in[6];
    const int*   item        = (const int*)d_in[7];

    mf_main<<<NB / WPB, TPB>>>(user_weight, item_weight, user_bias, item_bias,
                               bias, target, user, item, (float*)d_out);
}